// round 10
// baseline (speedup 1.0000x reference)
#include <cuda_runtime.h>
#include <cfloat>

#define BSZ   16
#define CAP   64
#define VOCAB 50265
#define TOPK  5
#define SEQL  256
#define ATQ   32
#define DIM   768
#define END_ID 2

// scratch (device globals: no allocation allowed)
__device__ __align__(16) float g_sce[BSZ * CAP * DIM];   // 3.1 MB
__device__ __align__(16) float g_att[BSZ * ATQ * DIM];   // 1.5 MB

// ---------------------------------------------------------------------------
// monotone float <-> uint mapping (unsigned order == float order)
// ---------------------------------------------------------------------------
__device__ __forceinline__ unsigned fordu(float x) {
    unsigned b = __float_as_uint(x);
    return b ^ (unsigned)(((int)b >> 31) | 0x80000000);
}
__device__ __forceinline__ float uford(unsigned u) {
    unsigned b = (u & 0x80000000u) ? (u ^ 0x80000000u) : ~u;
    return __uint_as_float(b);
}

// ---------------------------------------------------------------------------
// merge two sorted-descending top-5 lists (tie-break: lower index wins)
// ---------------------------------------------------------------------------
__device__ __forceinline__ void merge5(float v[5], int ix[5],
                                       const float ov[5], const int oi[5]) {
    float mv[5]; int mi[5];
    int a = 0, b = 0;
#pragma unroll
    for (int t = 0; t < 5; t++) {
        bool ta = (v[a] > ov[b]) || (v[a] == ov[b] && ix[a] < oi[b]);
        mv[t] = ta ? v[a] : ov[b];
        mi[t] = ta ? ix[a] : oi[b];
        a += ta ? 1 : 0;
        b += ta ? 0 : 1;
    }
#pragma unroll
    for (int t = 0; t < 5; t++) { v[t] = mv[t]; ix[t] = mi[t]; }
}

__device__ __forceinline__ void insert5(float bv[5], int bi[5], float& v4,
                                        float x, int j) {
    if (x > v4) {
        bv[4] = x; bi[4] = j;
#pragma unroll
        for (int q = 4; q > 0; q--) {
            if (bv[q] > bv[q - 1]) {
                float tv = bv[q]; bv[q] = bv[q - 1]; bv[q - 1] = tv;
                int   ti = bi[q]; bi[q] = bi[q - 1]; bi[q - 1] = ti;
            }
        }
        v4 = bv[4];
    }
}

// exact concurrent sorted-top-5 insert via atomicMax bubble cascade.
// key = mono(value)<<32 | (0x7FFFFFFF - index)  (desc value, lower idx wins ties)
// __noinline__: cold path (~46 executions/row) — keeps its registers out of
// the hot-loop allocation (R9: regs 109 -> 37).
__device__ __noinline__ void slot_insert(unsigned long long* slots,
                                         volatile float* st,
                                         float x, int j) {
    unsigned long long key =
        ((unsigned long long)fordu(x) << 32) | (unsigned)(0x7FFFFFFF - j);
#pragma unroll
    for (int i = 0; i < 5; i++) {
        unsigned long long old = atomicMax(&slots[i], key);
        key = old < key ? old : key;     // carry the smaller downward
    }
    // refresh mirror threshold (benign race; any past slot[4] is a valid
    // lower bound; uford(0) is NaN and fmaxf ignores NaN)
    float fifth = uford((unsigned)(slots[4] >> 32));
    *st = fmaxf(*st, fifth);
}

// ---------------------------------------------------------------------------
// Kernel 1: per (b,c) row: exact top-5 via shared-threshold screening,
// then softmax(top5) + weighted embedding mix.
// grid = BSZ*CAP blocks, 256 threads, 4 CTAs/SM floor.
// R10 experiment: MLP_p1 4 -> 8 (8 x LDG.128 per iter) at held occupancy.
// ---------------------------------------------------------------------------
__global__ void __launch_bounds__(256, 4) topk_sce_kernel(
    const float* __restrict__ caption_out,   // [BSZ, CAP, VOCAB]
    const float* __restrict__ embed_table)   // [VOCAB, DIM]
{
    const int row = blockIdx.x;              // b*CAP + c
    const int tid = threadIdx.x;
    const int lane = tid & 31;
    const int wid  = tid >> 5;
    const float* rp = caption_out + (long long)row * VOCAB;

    __shared__ unsigned long long s_slot[5];
    __shared__ volatile float s_t;

    if (tid < 5) s_slot[tid] = 0ull;

    // ---- seed: warp 0 computes 5th-largest of first 256 elements -> s_t ----
    if (wid == 0) {
        float bv[5]; int bi[5];
#pragma unroll
        for (int t = 0; t < 5; t++) { bv[t] = -FLT_MAX; bi[t] = 0x7fffffff; }
        float v4 = -FLT_MAX;
#pragma unroll
        for (int u = 0; u < 8; u++) {
            int j = lane + 32 * u;
            insert5(bv, bi, v4, __ldg(rp + j), j);
        }
#pragma unroll
        for (int off = 1; off < 32; off <<= 1) {
            float ov[5]; int oi[5];
#pragma unroll
            for (int t = 0; t < 5; t++) {
                ov[t] = __shfl_xor_sync(0xffffffffu, bv[t], off);
                oi[t] = __shfl_xor_sync(0xffffffffu, bi[t], off);
            }
            merge5(bv, bi, ov, oi);
        }
        if (lane == 0) s_t = bv[4];      // lower bound of final 5th-best
    }
    __syncthreads();

    // ---- alignment prologue (row stride 50265 floats cycles mod 4) ----
    const int pro = (4 - (row & 3)) & 3;
    const float4* rp4 = (const float4*)(rp + pro);
    const int nvec = (VOCAB - pro) >> 2;     // 12565 or 12566

    if (tid < pro) {
        float x = __ldg(rp + tid);
        float t = s_t;
        if (x >= t) slot_insert(s_slot, &s_t, x, tid);
    }

    // ---- main loop: 32 elements/thread/iter (8 x float4), 6 full iters ----
    // caption_out is a one-shot 206MB stream: streaming loads (__ldcs) keep
    // it from thrashing L2 (g_sce + embed rows benefit from residency).
    int base = 0;
#pragma unroll 1
    for (int it = 0; it < 6; it++) {
        float4 a[8];
#pragma unroll
        for (int u = 0; u < 8; u++) a[u] = __ldcs(rp4 + base + tid + 256 * u);

        float pm[8];
#pragma unroll
        for (int u = 0; u < 8; u++)
            pm[u] = fmaxf(fmaxf(a[u].x, a[u].y), fmaxf(a[u].z, a[u].w));
        float m = fmaxf(fmaxf(fmaxf(pm[0], pm[1]), fmaxf(pm[2], pm[3])),
                        fmaxf(fmaxf(pm[4], pm[5]), fmaxf(pm[6], pm[7])));

        float t = s_t;
        if (m >= t) {                    // rare
#pragma unroll
            for (int u = 0; u < 8; u++) {
                int j0 = pro + 4 * (base + tid + 256 * u);
                if (a[u].x >= t) slot_insert(s_slot, &s_t, a[u].x, j0);
                if (a[u].y >= t) slot_insert(s_slot, &s_t, a[u].y, j0 + 1);
                if (a[u].z >= t) slot_insert(s_slot, &s_t, a[u].z, j0 + 2);
                if (a[u].w >= t) slot_insert(s_slot, &s_t, a[u].w, j0 + 3);
            }
        }
        base += 2048;
    }

    // ---- tail float4s (g in [12288, nvec)) ----
    for (int g = 6 * 2048 + tid; g < nvec; g += 256) {
        float4 a = __ldcs(rp4 + g);
        float m = fmaxf(fmaxf(a.x, a.y), fmaxf(a.z, a.w));
        float t = s_t;
        if (m >= t) {
            int j0 = pro + 4 * g;
            if (a.x >= t) slot_insert(s_slot, &s_t, a.x, j0);
            if (a.y >= t) slot_insert(s_slot, &s_t, a.y, j0 + 1);
            if (a.z >= t) slot_insert(s_slot, &s_t, a.z, j0 + 2);
            if (a.w >= t) slot_insert(s_slot, &s_t, a.w, j0 + 3);
        }
    }
    // ---- scalar tail ----
    for (int j = pro + 4 * nvec + tid; j < VOCAB; j += 256) {
        float x = __ldg(rp + j);
        float t = s_t;
        if (x >= t) slot_insert(s_slot, &s_t, x, j);
    }
    __syncthreads();

    // ---- unpack sorted top-5, softmax, embedding mix ----
    float vals[5]; int ids[5];
#pragma unroll
    for (int t = 0; t < 5; t++) {
        unsigned long long k = s_slot[t];
        vals[t] = uford((unsigned)(k >> 32));
        ids[t]  = 0x7FFFFFFF - (int)(unsigned)(k & 0xFFFFFFFFu);
    }
    float w[5];
    {
        float mx = vals[0];
        float s = 0.f;
#pragma unroll
        for (int t = 0; t < 5; t++) { w[t] = expf(vals[t] - mx); s += w[t]; }
        float inv = 1.0f / s;
#pragma unroll
        for (int t = 0; t < 5; t++) w[t] *= inv;
    }
    if (tid < 192) {   // 192 * float4 = 768
        const float4* e0 = (const float4*)(embed_table + (long long)ids[0] * DIM);
        const float4* e1 = (const float4*)(embed_table + (long long)ids[1] * DIM);
        const float4* e2 = (const float4*)(embed_table + (long long)ids[2] * DIM);
        const float4* e3 = (const float4*)(embed_table + (long long)ids[3] * DIM);
        const float4* e4 = (const float4*)(embed_table + (long long)ids[4] * DIM);
        float4 r0 = __ldg(e0 + tid), r1 = __ldg(e1 + tid), r2 = __ldg(e2 + tid),
               r3 = __ldg(e3 + tid), r4 = __ldg(e4 + tid);
        float4 o;
        o.x = w[0]*r0.x + w[1]*r1.x + w[2]*r2.x + w[3]*r3.x + w[4]*r4.x;
        o.y = w[0]*r0.y + w[1]*r1.y + w[2]*r2.y + w[3]*r3.y + w[4]*r4.y;
        o.z = w[0]*r0.z + w[1]*r1.z + w[2]*r2.z + w[3]*r3.z + w[4]*r4.z;
        o.w = w[0]*r0.w + w[1]*r1.w + w[2]*r2.w + w[3]*r3.w + w[4]*r4.w;
        ((float4*)(g_sce + (long long)row * DIM))[tid] = o;
    }
}

// ---------------------------------------------------------------------------
// Kernel 2: attention. grid = (BSZ, ATQ/2), 256 threads; 2 queries per block.
// ---------------------------------------------------------------------------
__global__ void __launch_bounds__(256) attn_kernel(
    const float* __restrict__ q_in,          // [BSZ, ATQ, DIM]
    const int*   __restrict__ caption_len)   // [BSZ]
{
    const int b  = blockIdx.x;
    const int q0 = blockIdx.y * 2;
    const int tid = threadIdx.x;
    const int lane = tid & 31;
    const int wid  = tid >> 5;
    const float SCALE = 0.03608439182435161f;  // 1/sqrt(768)

    const float4* qp0 = (const float4*)(q_in + ((long long)(b * ATQ + q0)) * DIM);
    const float4* qp1 = qp0 + DIM / 4;
    const float*  sce = g_sce + (long long)b * CAP * DIM;

    __shared__ float s_scores[2][CAP];
    __shared__ float s_attn[2][CAP];

    // preload both q rows into registers: lane covers float4 index lane + 32*t
    float4 q0r[6], q1r[6];
#pragma unroll
    for (int t = 0; t < 6; t++) {
        q0r[t] = __ldg(qp0 + lane + 32 * t);
        q1r[t] = __ldg(qp1 + lane + 32 * t);
    }

    // scores: warp w handles keys k = w*8 .. w*8+7 for both queries
#pragma unroll
    for (int kk = 0; kk < 8; kk++) {
        int k = wid * 8 + kk;
        const float4* sp = (const float4*)(sce + (long long)k * DIM);
        float a0 = 0.f, a1 = 0.f;
#pragma unroll
        for (int t = 0; t < 6; t++) {
            float4 s = __ldg(sp + lane + 32 * t);
            a0 += q0r[t].x * s.x + q0r[t].y * s.y + q0r[t].z * s.z + q0r[t].w * s.w;
            a1 += q1r[t].x * s.x + q1r[t].y * s.y + q1r[t].z * s.z + q1r[t].w * s.w;
        }
#pragma unroll
        for (int off = 16; off; off >>= 1) {
            a0 += __shfl_xor_sync(0xffffffffu, a0, off);
            a1 += __shfl_xor_sync(0xffffffffu, a1, off);
        }
        if (lane == 0) { s_scores[0][k] = a0; s_scores[1][k] = a1; }
    }
    __syncthreads();

    // softmax (masked) — warp 0 handles q0, warp 1 handles q1
    if (wid < 2) {
        int clen = caption_len[b];
        float x0 = (lane      < clen) ? s_scores[wid][lane]      * SCALE : -1e9f;
        float x1 = (lane + 32 < clen) ? s_scores[wid][lane + 32] * SCALE : -1e9f;
        float m = fmaxf(x0, x1);
#pragma unroll
        for (int off = 16; off; off >>= 1) m = fmaxf(m, __shfl_xor_sync(0xffffffffu, m, off));
        float e0 = expf(x0 - m), e1 = expf(x1 - m);
        float s = e0 + e1;
#pragma unroll
        for (int off = 16; off; off >>= 1) s += __shfl_xor_sync(0xffffffffu, s, off);
        float inv = 1.0f / s;
        s_attn[wid][lane]      = e0 * inv;
        s_attn[wid][lane + 32] = e1 * inv;
    }
    __syncthreads();

    // AV: threads 0..191 each own one float4 of the 768-dim output
    if (tid < 192) {
        float4 acc0 = {0.f, 0.f, 0.f, 0.f};
        float4 acc1 = {0.f, 0.f, 0.f, 0.f};
        const float4* sp = (const float4*)sce;
#pragma unroll 4
        for (int k = 0; k < CAP; k++) {
            float a0 = s_attn[0][k];
            float a1 = s_attn[1][k];
            float4 s = __ldg(sp + k * (DIM / 4) + tid);
            acc0.x += a0 * s.x; acc0.y += a0 * s.y; acc0.z += a0 * s.z; acc0.w += a0 * s.w;
            acc1.x += a1 * s.x; acc1.y += a1 * s.y; acc1.z += a1 * s.z; acc1.w += a1 * s.w;
        }
        float4* o0 = (float4*)(g_att + ((long long)(b * ATQ + q0)) * DIM);
        float4* o1 = o0 + DIM / 4;
        o0[tid] = acc0;
        o1[tid] = acc1;
    }
}

// ---------------------------------------------------------------------------
// Kernel 3: variable-length scatter. grid = (SEQL, BSZ), 192 threads (float4)
// ---------------------------------------------------------------------------
__global__ void __launch_bounds__(192) scatter_kernel(
    const float* __restrict__ embed_table,   // [VOCAB, DIM]
    const int*   __restrict__ input_ids,     // [BSZ, SEQL]
    const int*   __restrict__ origin_len,    // [BSZ]
    const int*   __restrict__ target_len,    // [BSZ]
    float*       __restrict__ out)           // [BSZ, SEQL, DIM]
{
    const int s = blockIdx.x;
    const int b = blockIdx.y;
    const int t = threadIdx.x;

    const int rel = s - origin_len[b];
    const int tl  = target_len[b];

    const float4* src;
    if (rel >= 0 && rel < tl) {
        src = (const float4*)(g_att + ((long long)(b * ATQ + rel)) * DIM);
    } else if (rel == tl) {
        src = (const float4*)(embed_table + (long long)END_ID * DIM);
    } else {
        int id = input_ids[b * SEQL + s];
        src = (const float4*)(embed_table + (long long)id * DIM);
    }
    float4* dst = (float4*)(out + ((long long)(b * SEQL + s)) * DIM);
    dst[t] = src[t];
}

// ---------------------------------------------------------------------------
extern "C" void kernel_launch(void* const* d_in, const int* in_sizes, int n_in,
                              void* d_out, int out_size) {
    const float* caption_out      = (const float*)d_in[0];  // [16,64,50265] f32
    const float* embed_table      = (const float*)d_in[1];  // [50265,768] f32
    const float* inputs_embeds_at = (const float*)d_in[2];  // [16,32,768] f32
    const int*   input_ids        = (const int*)  d_in[3];  // [16,256] i32
    const int*   origin_len       = (const int*)  d_in[4];  // [16] i32
    const int*   target_len       = (const int*)  d_in[5];  // [16] i32
    const int*   caption_len      = (const int*)  d_in[6];  // [16] i32
    float* out = (float*)d_out;

    topk_sce_kernel<<<BSZ * CAP, 256>>>(caption_out, embed_table);
    attn_kernel<<<dim3(BSZ, ATQ / 2), 256>>>(inputs_embeds_at, caption_len);
    scatter_kernel<<<dim3(SEQL, BSZ), 192>>>(embed_table, input_ids,
                                             origin_len, target_len, out);
}

// round 11
// speedup vs baseline: 1.4299x; 1.4299x over previous
#include <cuda_runtime.h>
#include <cfloat>

#define BSZ   16
#define CAP   64
#define VOCAB 50265
#define TOPK  5
#define SEQL  256
#define ATQ   32
#define DIM   768
#define END_ID 2

// scratch (device globals: no allocation allowed)
__device__ __align__(16) float g_sce[BSZ * CAP * DIM];   // 3.1 MB
__device__ __align__(16) float g_att[BSZ * ATQ * DIM];   // 1.5 MB

// ---------------------------------------------------------------------------
// monotone float <-> uint mapping (unsigned order == float order)
// ---------------------------------------------------------------------------
__device__ __forceinline__ unsigned fordu(float x) {
    unsigned b = __float_as_uint(x);
    return b ^ (unsigned)(((int)b >> 31) | 0x80000000);
}
__device__ __forceinline__ float uford(unsigned u) {
    unsigned b = (u & 0x80000000u) ? (u ^ 0x80000000u) : ~u;
    return __uint_as_float(b);
}

// ---------------------------------------------------------------------------
// merge two sorted-descending top-5 lists (tie-break: lower index wins)
// ---------------------------------------------------------------------------
__device__ __forceinline__ void merge5(float v[5], int ix[5],
                                       const float ov[5], const int oi[5]) {
    float mv[5]; int mi[5];
    int a = 0, b = 0;
#pragma unroll
    for (int t = 0; t < 5; t++) {
        bool ta = (v[a] > ov[b]) || (v[a] == ov[b] && ix[a] < oi[b]);
        mv[t] = ta ? v[a] : ov[b];
        mi[t] = ta ? ix[a] : oi[b];
        a += ta ? 1 : 0;
        b += ta ? 0 : 1;
    }
#pragma unroll
    for (int t = 0; t < 5; t++) { v[t] = mv[t]; ix[t] = mi[t]; }
}

__device__ __forceinline__ void insert5(float bv[5], int bi[5], float& v4,
                                        float x, int j) {
    if (x > v4) {
        bv[4] = x; bi[4] = j;
#pragma unroll
        for (int q = 4; q > 0; q--) {
            if (bv[q] > bv[q - 1]) {
                float tv = bv[q]; bv[q] = bv[q - 1]; bv[q - 1] = tv;
                int   ti = bi[q]; bi[q] = bi[q - 1]; bi[q - 1] = ti;
            }
        }
        v4 = bv[4];
    }
}

// exact concurrent sorted-top-5 insert via atomicMax bubble cascade.
// key = mono(value)<<32 | (0x7FFFFFFF - index)  (desc value, lower idx wins ties)
// __noinline__: cold path (~46 executions/row) — keeps its registers out of
// the hot-loop allocation (R9: regs 109 -> 37).
__device__ __noinline__ void slot_insert(unsigned long long* slots,
                                         volatile float* st,
                                         float x, int j) {
    unsigned long long key =
        ((unsigned long long)fordu(x) << 32) | (unsigned)(0x7FFFFFFF - j);
#pragma unroll
    for (int i = 0; i < 5; i++) {
        unsigned long long old = atomicMax(&slots[i], key);
        key = old < key ? old : key;     // carry the smaller downward
    }
    // refresh mirror threshold (benign race; any past slot[4] is a valid
    // lower bound; uford(0) is NaN and fmaxf ignores NaN)
    float fifth = uford((unsigned)(slots[4] >> 32));
    *st = fmaxf(*st, fifth);
}

// ---------------------------------------------------------------------------
// Kernel 1: per (b,c) row: exact top-5 via shared-threshold screening,
// then softmax(top5) + weighted embedding mix.
// grid = BSZ*CAP blocks, 256 threads.
// R11 experiment: force 8 CTAs/SM (<=32 regs) — occupancy is the proven lever
// (R8 15w/SM->2.3TB/s, R10 29->3.2, R9 42->3.6; per-warp rate falls w/ load).
// ---------------------------------------------------------------------------
__global__ void __launch_bounds__(256, 8) topk_sce_kernel(
    const float* __restrict__ caption_out,   // [BSZ, CAP, VOCAB]
    const float* __restrict__ embed_table)   // [VOCAB, DIM]
{
    const int row = blockIdx.x;              // b*CAP + c
    const int tid = threadIdx.x;
    const int lane = tid & 31;
    const int wid  = tid >> 5;
    const float* rp = caption_out + (long long)row * VOCAB;

    __shared__ unsigned long long s_slot[5];
    __shared__ volatile float s_t;

    if (tid < 5) s_slot[tid] = 0ull;

    // ---- seed: warp 0 computes 5th-largest of first 256 elements -> s_t ----
    if (wid == 0) {
        float bv[5]; int bi[5];
#pragma unroll
        for (int t = 0; t < 5; t++) { bv[t] = -FLT_MAX; bi[t] = 0x7fffffff; }
        float v4 = -FLT_MAX;
#pragma unroll
        for (int u = 0; u < 8; u++) {
            int j = lane + 32 * u;
            insert5(bv, bi, v4, __ldg(rp + j), j);
        }
#pragma unroll
        for (int off = 1; off < 32; off <<= 1) {
            float ov[5]; int oi[5];
#pragma unroll
            for (int t = 0; t < 5; t++) {
                ov[t] = __shfl_xor_sync(0xffffffffu, bv[t], off);
                oi[t] = __shfl_xor_sync(0xffffffffu, bi[t], off);
            }
            merge5(bv, bi, ov, oi);
        }
        if (lane == 0) s_t = bv[4];      // lower bound of final 5th-best
    }
    __syncthreads();

    // ---- alignment prologue (row stride 50265 floats cycles mod 4) ----
    const int pro = (4 - (row & 3)) & 3;
    const float4* rp4 = (const float4*)(rp + pro);
    const int nvec = (VOCAB - pro) >> 2;     // 12565 or 12566

    if (tid < pro) {
        float x = __ldg(rp + tid);
        float t = s_t;
        if (x >= t) slot_insert(s_slot, &s_t, x, tid);
    }

    // ---- main loop: 16 elements/thread/iter (4 x float4), 12 full iters ----
    // caption_out is a one-shot 206MB stream: streaming loads (__ldcs) keep
    // it from thrashing L2 (g_sce + embed rows benefit from residency).
    int base = 0;
#pragma unroll 1
    for (int it = 0; it < 12; it++) {
        float4 a[4];
#pragma unroll
        for (int u = 0; u < 4; u++) a[u] = __ldcs(rp4 + base + tid + 256 * u);

        float pm[4];
#pragma unroll
        for (int u = 0; u < 4; u++)
            pm[u] = fmaxf(fmaxf(a[u].x, a[u].y), fmaxf(a[u].z, a[u].w));
        float m = fmaxf(fmaxf(pm[0], pm[1]), fmaxf(pm[2], pm[3]));

        float t = s_t;
        if (m >= t) {                    // rare
#pragma unroll
            for (int u = 0; u < 4; u++) {
                int j0 = pro + 4 * (base + tid + 256 * u);
                if (a[u].x >= t) slot_insert(s_slot, &s_t, a[u].x, j0);
                if (a[u].y >= t) slot_insert(s_slot, &s_t, a[u].y, j0 + 1);
                if (a[u].z >= t) slot_insert(s_slot, &s_t, a[u].z, j0 + 2);
                if (a[u].w >= t) slot_insert(s_slot, &s_t, a[u].w, j0 + 3);
            }
        }
        base += 1024;
    }

    // ---- tail float4s (g in [12288, nvec)) ----
    for (int g = 12 * 1024 + tid; g < nvec; g += 256) {
        float4 a = __ldcs(rp4 + g);
        float m = fmaxf(fmaxf(a.x, a.y), fmaxf(a.z, a.w));
        float t = s_t;
        if (m >= t) {
            int j0 = pro + 4 * g;
            if (a.x >= t) slot_insert(s_slot, &s_t, a.x, j0);
            if (a.y >= t) slot_insert(s_slot, &s_t, a.y, j0 + 1);
            if (a.z >= t) slot_insert(s_slot, &s_t, a.z, j0 + 2);
            if (a.w >= t) slot_insert(s_slot, &s_t, a.w, j0 + 3);
        }
    }
    // ---- scalar tail ----
    for (int j = pro + 4 * nvec + tid; j < VOCAB; j += 256) {
        float x = __ldg(rp + j);
        float t = s_t;
        if (x >= t) slot_insert(s_slot, &s_t, x, j);
    }
    __syncthreads();

    // ---- unpack sorted top-5, softmax, embedding mix ----
    float vals[5]; int ids[5];
#pragma unroll
    for (int t = 0; t < 5; t++) {
        unsigned long long k = s_slot[t];
        vals[t] = uford((unsigned)(k >> 32));
        ids[t]  = 0x7FFFFFFF - (int)(unsigned)(k & 0xFFFFFFFFu);
    }
    float w[5];
    {
        float mx = vals[0];
        float s = 0.f;
#pragma unroll
        for (int t = 0; t < 5; t++) { w[t] = expf(vals[t] - mx); s += w[t]; }
        float inv = 1.0f / s;
#pragma unroll
        for (int t = 0; t < 5; t++) w[t] *= inv;
    }
    if (tid < 192) {   // 192 * float4 = 768
        const float4* e0 = (const float4*)(embed_table + (long long)ids[0] * DIM);
        const float4* e1 = (const float4*)(embed_table + (long long)ids[1] * DIM);
        const float4* e2 = (const float4*)(embed_table + (long long)ids[2] * DIM);
        const float4* e3 = (const float4*)(embed_table + (long long)ids[3] * DIM);
        const float4* e4 = (const float4*)(embed_table + (long long)ids[4] * DIM);
        float4 r0 = __ldg(e0 + tid), r1 = __ldg(e1 + tid), r2 = __ldg(e2 + tid),
               r3 = __ldg(e3 + tid), r4 = __ldg(e4 + tid);
        float4 o;
        o.x = w[0]*r0.x + w[1]*r1.x + w[2]*r2.x + w[3]*r3.x + w[4]*r4.x;
        o.y = w[0]*r0.y + w[1]*r1.y + w[2]*r2.y + w[3]*r3.y + w[4]*r4.y;
        o.z = w[0]*r0.z + w[1]*r1.z + w[2]*r2.z + w[3]*r3.z + w[4]*r4.z;
        o.w = w[0]*r0.w + w[1]*r1.w + w[2]*r2.w + w[3]*r3.w + w[4]*r4.w;
        ((float4*)(g_sce + (long long)row * DIM))[tid] = o;
    }
}

// ---------------------------------------------------------------------------
// Kernel 2: attention. grid = (BSZ, ATQ/2), 256 threads; 2 queries per block.
// ---------------------------------------------------------------------------
__global__ void __launch_bounds__(256) attn_kernel(
    const float* __restrict__ q_in,          // [BSZ, ATQ, DIM]
    const int*   __restrict__ caption_len)   // [BSZ]
{
    const int b  = blockIdx.x;
    const int q0 = blockIdx.y * 2;
    const int tid = threadIdx.x;
    const int lane = tid & 31;
    const int wid  = tid >> 5;
    const float SCALE = 0.03608439182435161f;  // 1/sqrt(768)

    const float4* qp0 = (const float4*)(q_in + ((long long)(b * ATQ + q0)) * DIM);
    const float4* qp1 = qp0 + DIM / 4;
    const float*  sce = g_sce + (long long)b * CAP * DIM;

    __shared__ float s_scores[2][CAP];
    __shared__ float s_attn[2][CAP];

    // preload both q rows into registers: lane covers float4 index lane + 32*t
    float4 q0r[6], q1r[6];
#pragma unroll
    for (int t = 0; t < 6; t++) {
        q0r[t] = __ldg(qp0 + lane + 32 * t);
        q1r[t] = __ldg(qp1 + lane + 32 * t);
    }

    // scores: warp w handles keys k = w*8 .. w*8+7 for both queries
#pragma unroll
    for (int kk = 0; kk < 8; kk++) {
        int k = wid * 8 + kk;
        const float4* sp = (const float4*)(sce + (long long)k * DIM);
        float a0 = 0.f, a1 = 0.f;
#pragma unroll
        for (int t = 0; t < 6; t++) {
            float4 s = __ldg(sp + lane + 32 * t);
            a0 += q0r[t].x * s.x + q0r[t].y * s.y + q0r[t].z * s.z + q0r[t].w * s.w;
            a1 += q1r[t].x * s.x + q1r[t].y * s.y + q1r[t].z * s.z + q1r[t].w * s.w;
        }
#pragma unroll
        for (int off = 16; off; off >>= 1) {
            a0 += __shfl_xor_sync(0xffffffffu, a0, off);
            a1 += __shfl_xor_sync(0xffffffffu, a1, off);
        }
        if (lane == 0) { s_scores[0][k] = a0; s_scores[1][k] = a1; }
    }
    __syncthreads();

    // softmax (masked) — warp 0 handles q0, warp 1 handles q1
    if (wid < 2) {
        int clen = caption_len[b];
        float x0 = (lane      < clen) ? s_scores[wid][lane]      * SCALE : -1e9f;
        float x1 = (lane + 32 < clen) ? s_scores[wid][lane + 32] * SCALE : -1e9f;
        float m = fmaxf(x0, x1);
#pragma unroll
        for (int off = 16; off; off >>= 1) m = fmaxf(m, __shfl_xor_sync(0xffffffffu, m, off));
        float e0 = expf(x0 - m), e1 = expf(x1 - m);
        float s = e0 + e1;
#pragma unroll
        for (int off = 16; off; off >>= 1) s += __shfl_xor_sync(0xffffffffu, s, off);
        float inv = 1.0f / s;
        s_attn[wid][lane]      = e0 * inv;
        s_attn[wid][lane + 32] = e1 * inv;
    }
    __syncthreads();

    // AV: threads 0..191 each own one float4 of the 768-dim output
    if (tid < 192) {
        float4 acc0 = {0.f, 0.f, 0.f, 0.f};
        float4 acc1 = {0.f, 0.f, 0.f, 0.f};
        const float4* sp = (const float4*)sce;
#pragma unroll 4
        for (int k = 0; k < CAP; k++) {
            float a0 = s_attn[0][k];
            float a1 = s_attn[1][k];
            float4 s = __ldg(sp + k * (DIM / 4) + tid);
            acc0.x += a0 * s.x; acc0.y += a0 * s.y; acc0.z += a0 * s.z; acc0.w += a0 * s.w;
            acc1.x += a1 * s.x; acc1.y += a1 * s.y; acc1.z += a1 * s.z; acc1.w += a1 * s.w;
        }
        float4* o0 = (float4*)(g_att + ((long long)(b * ATQ + q0)) * DIM);
        float4* o1 = o0 + DIM / 4;
        o0[tid] = acc0;
        o1[tid] = acc1;
    }
}

// ---------------------------------------------------------------------------
// Kernel 3: variable-length scatter. grid = (SEQL, BSZ), 192 threads (float4)
// ---------------------------------------------------------------------------
__global__ void __launch_bounds__(192) scatter_kernel(
    const float* __restrict__ embed_table,   // [VOCAB, DIM]
    const int*   __restrict__ input_ids,     // [BSZ, SEQL]
    const int*   __restrict__ origin_len,    // [BSZ]
    const int*   __restrict__ target_len,    // [BSZ]
    float*       __restrict__ out)           // [BSZ, SEQL, DIM]
{
    const int s = blockIdx.x;
    const int b = blockIdx.y;
    const int t = threadIdx.x;

    const int rel = s - origin_len[b];
    const int tl  = target_len[b];

    const float4* src;
    if (rel >= 0 && rel < tl) {
        src = (const float4*)(g_att + ((long long)(b * ATQ + rel)) * DIM);
    } else if (rel == tl) {
        src = (const float4*)(embed_table + (long long)END_ID * DIM);
    } else {
        int id = input_ids[b * SEQL + s];
        src = (const float4*)(embed_table + (long long)id * DIM);
    }
    float4* dst = (float4*)(out + ((long long)(b * SEQL + s)) * DIM);
    dst[t] = src[t];
}

// ---------------------------------------------------------------------------
extern "C" void kernel_launch(void* const* d_in, const int* in_sizes, int n_in,
                              void* d_out, int out_size) {
    const float* caption_out      = (const float*)d_in[0];  // [16,64,50265] f32
    const float* embed_table      = (const float*)d_in[1];  // [50265,768] f32
    const float* inputs_embeds_at = (const float*)d_in[2];  // [16,32,768] f32
    const int*   input_ids        = (const int*)  d_in[3];  // [16,256] i32
    const int*   origin_len       = (const int*)  d_in[4];  // [16] i32
    const int*   target_len       = (const int*)  d_in[5];  // [16] i32
    const int*   caption_len      = (const int*)  d_in[6];  // [16] i32
    float* out = (float*)d_out;

    topk_sce_kernel<<<BSZ * CAP, 256>>>(caption_out, embed_table);
    attn_kernel<<<dim3(BSZ, ATQ / 2), 256>>>(inputs_embeds_at, caption_len);
    scatter_kernel<<<dim3(SEQL, BSZ), 192>>>(embed_table, input_ids,
                                             origin_len, target_len, out);
}